// round 1
// baseline (speedup 1.0000x reference)
#include <cuda_runtime.h>
#include <cuda_bf16.h>
#include <math.h>

// Problem constants
#define NB   8      // NUM_BLOCK (batch)
#define NT   500    // NUM_FRAME
#define NF   257    // NUM_BIN
#define NC   8      // NUM_CH
#define NNUL 4      // NUM_NULL
#define LOWF 5
#define HIGHF 70

#define FN   (NF*NNUL)          // 1028
#define DCF_SIZE (NB*NT*NF*NNUL) // 4,112,000

#define ALPHA_C  0.35f
#define ONEMA_C  0.65f

// chunked-scan parameters: alpha^32 ~ 2.8e-15, far below 1e-3 tolerance
#define TCHUNK 125
#define NCHUNK 4
#define WARMUP 32

// ------------------- scratch (device globals; no runtime allocation) -------
__device__ float g_pr[NB*NT*NF*NNUL];   // 16.45 MB
__device__ float g_pi[NB*NT*NF*NNUL];   // 16.45 MB
__device__ float g_pw[NB*NT*NF];        //  4.11 MB
__device__ float g_cr[NB*NF*NNUL];      // t=0 correction: ti0*ni0
__device__ float g_ci[NB*NF*NNUL];      // t=0 correction: tr0*ni0
__device__ float g_pre[NB*NT];          // sum_f psd  (band)
__device__ float g_aft[NB*NT*NNUL];     // sum_f phi  (band)

__device__ __forceinline__ float dot8(const float4 a0, const float4 a1,
                                      const float4 b0, const float4 b1) {
    return a0.x*b0.x + a0.y*b0.y + a0.z*b0.z + a0.w*b0.w
         + a1.x*b1.x + a1.y*b1.y + a1.z*b1.z + a1.w*b1.w;
}

// ------------------- K1: beamforming dots, fully parallel over (b,t,f) -----
__global__ void k1_beamform(const float* __restrict__ in,
                            const int*   __restrict__ beam_id,
                            const float* __restrict__ tw,
                            const float* __restrict__ nw,
                            float* __restrict__ out) {
    int idx = blockIdx.x * blockDim.x + threadIdx.x;

    // zero the band-sum accumulators (K2 atomics depend on this; K2 launches after K1)
    if (idx < NB*NT)      g_pre[idx] = 0.0f;
    if (idx < NB*NT*NNUL) g_aft[idx] = 0.0f;

    if (idx >= NB*NT*NF) return;

    int f  = idx % NF;
    int bt = idx / NF;        // b*NT + t
    int t  = bt % NT;
    int b  = bt / NT;
    int beam = beam_id[b];

    // input layout (B, T, 2, F, C), C contiguous, 32B-aligned groups of 8
    const float* xrp = in + ((size_t)bt * 2 + 0) * (NF*NC) + f*NC;
    const float* xip = in + ((size_t)bt * 2 + 1) * (NF*NC) + f*NC;
    float4 xr0 = ((const float4*)xrp)[0], xr1 = ((const float4*)xrp)[1];
    float4 xi0 = ((const float4*)xip)[0], xi1 = ((const float4*)xip)[1];

    // target weights (BEAM, 2, F, C)
    const float* twrp = tw + ((beam*2 + 0)*NF + f)*NC;
    const float* twip = tw + ((beam*2 + 1)*NF + f)*NC;
    float4 twr0 = ((const float4*)twrp)[0], twr1 = ((const float4*)twrp)[1];
    float4 twi0 = ((const float4*)twip)[0], twi1 = ((const float4*)twip)[1];

    float tr = dot8(xr0,xr1, twr0,twr1) - dot8(xi0,xi1, twi0,twi1);
    float ti = dot8(xr0,xr1, twi0,twi1) + dot8(xi0,xi1, twr0,twr1);

    float pw = (dot8(xr0,xr1, xr0,xr1) + dot8(xi0,xi1, xi0,xi1)) * 0.125f;

    float prv[NNUL], piv[NNUL], niv[NNUL];
    #pragma unroll
    for (int n = 0; n < NNUL; n++) {
        // null weights (BEAM, NNUL, 2, F, C)
        const float* nwrp = nw + (((beam*NNUL + n)*2 + 0)*NF + f)*NC;
        const float* nwip = nw + (((beam*NNUL + n)*2 + 1)*NF + f)*NC;
        float4 nwr0 = ((const float4*)nwrp)[0], nwr1 = ((const float4*)nwrp)[1];
        float4 nwi0 = ((const float4*)nwip)[0], nwi1 = ((const float4*)nwip)[1];
        float nr = dot8(xr0,xr1, nwr0,nwr1) - dot8(xi0,xi1, nwi0,nwi1);
        float ni = dot8(xr0,xr1, nwi0,nwi1) + dot8(xi0,xi1, nwr0,nwr1);
        prv[n] = tr*nr + ti*ni;
        piv[n] = ti*nr - tr*ni;
        niv[n] = ni;
    }

    int o = (bt*NF + f) * NNUL;
    *(float4*)(g_pr + o) = make_float4(prv[0], prv[1], prv[2], prv[3]);
    *(float4*)(g_pi + o) = make_float4(piv[0], piv[1], piv[2], piv[3]);
    g_pw[bt*NF + f] = pw;

    // targ_out = stack([tr, ti], axis=2) -> (B, T, 2, F), after dcf in d_out
    out[DCF_SIZE + (bt*2 + 0)*NF + f] = tr;
    out[DCF_SIZE + (bt*2 + 1)*NF + f] = ti;

    if (t == 0) {
        // reference's t=0 quirk: phi_r0 = (1-a)*tr0*nr0 + ti0*ni0
        //                              = (1-a)*pr0 + a*(ti0*ni0)
        //                       phi_i0 = (1-a)*pi0 - a*(tr0*ni0)
        int o2 = (b*NF + f) * NNUL;
        float crv[NNUL], civ[NNUL];
        #pragma unroll
        for (int n = 0; n < NNUL; n++) { crv[n] = ti*niv[n]; civ[n] = tr*niv[n]; }
        *(float4*)(g_cr + o2) = make_float4(crv[0], crv[1], crv[2], crv[3]);
        *(float4*)(g_ci + o2) = make_float4(civ[0], civ[1], civ[2], civ[3]);
    }
}

// ------------------- K2: chunked EMA scan -----------------------------------
__global__ void k2_scan(float* __restrict__ out) {
    int gid = blockIdx.x * blockDim.x + threadIdx.x;
    const int PER = NB*NF*NNUL;   // 8224 states
    if (gid >= PER*NCHUNK) return;

    int c = gid / PER;
    int r = gid % PER;
    int n = r % NNUL;
    int f = (r / NNUL) % NF;
    int b = r / (NNUL*NF);

    int fo = f*NNUL + n;
    const float* pr = g_pr + b*NT*FN + fo;
    const float* pi = g_pi + b*NT*FN + fo;
    const float* pw = g_pw + b*NT*NF + f;
    float* dout = out + b*NT*FN + fo;   // dcf lives at start of d_out

    float phi_r, phi_i, psd;
    int t0 = c * TCHUNK;
    int tstart;

    if (c == 0) {
        float pr0 = pr[0], pi0 = pi[0], pw0 = pw[0];
        float cr = g_cr[(b*NF + f)*NNUL + n];
        float ci = g_ci[(b*NF + f)*NNUL + n];
        phi_r = ONEMA_C*pr0 + ALPHA_C*cr;
        phi_i = ONEMA_C*pi0 - ALPHA_C*ci;
        psd   = ONEMA_C*pw0;
        float phi = sqrtf(phi_r*phi_r + phi_i*phi_i);
        float q = phi / (psd + 1e-13f);
        q = fminf(fmaxf(q, 0.01f), 1.0f);
        dout[0] = q;                       // t=0: no ratio, no sqrt
        tstart = 1;
    } else {
        phi_r = 0.0f; phi_i = 0.0f; psd = 0.0f;
        #pragma unroll 8
        for (int s = t0 - WARMUP; s < t0; s++) {
            phi_r = ALPHA_C*phi_r + ONEMA_C*pr[s*FN];
            phi_i = ALPHA_C*phi_i + ONEMA_C*pi[s*FN];
            psd   = ALPHA_C*psd   + ONEMA_C*pw[s*NF];
        }
        tstart = t0;
    }

    bool inband = (f >= LOWF) && (f < HIGHF);
    float* aftp = g_aft + (b*NT)*NNUL + n;
    float* prep = g_pre + b*NT;

    #pragma unroll 4
    for (int t = tstart; t < t0 + TCHUNK; t++) {
        float prt = pr[t*FN];
        float pit = pi[t*FN];
        float pwt = pw[t*NF];
        phi_r = ALPHA_C*phi_r + ONEMA_C*prt;
        phi_i = ALPHA_C*phi_i + ONEMA_C*pit;
        psd   = ALPHA_C*psd   + ONEMA_C*pwt;
        float phi = sqrtf(phi_r*phi_r + phi_i*phi_i);
        float q = phi / (psd + 1e-13f);
        q = fminf(fmaxf(q, 0.01f), 1.0f);
        dout[t*FN] = q;                    // pre-ratio dcf; K3 finishes it
        if (inband) {
            atomicAdd(aftp + t*NNUL, phi);
            if (n == 0) atomicAdd(prep + t, psd);
        }
    }
}

// ------------------- K3: apply cross-frequency ratio (t >= 1) ---------------
__global__ void k3_ratio(float* __restrict__ out) {
    int idx = blockIdx.x * blockDim.x + threadIdx.x;
    if (idx >= DCF_SIZE) return;
    int n  = idx % NNUL;
    int bt = idx / FN;
    int t  = bt % NT;
    if (t == 0) return;
    float aft = g_aft[bt*NNUL + n];
    float pre = g_pre[bt];
    float ratio = aft / (pre + 1e-10f);
    ratio = fminf(fmaxf(ratio, 0.01f), 1.0f);
    out[idx] = sqrtf(out[idx] * ratio);
}

// ------------------- launcher ------------------------------------------------
extern "C" void kernel_launch(void* const* d_in, const int* in_sizes, int n_in,
                              void* d_out, int out_size) {
    const float* in      = (const float*)d_in[0];
    const int*   beam_id = (const int*)  d_in[1];
    const float* tw      = (const float*)d_in[2];
    const float* nw      = (const float*)d_in[3];
    float* out = (float*)d_out;

    {   // K1: one thread per (b,t,f)
        int total = NB*NT*NF;
        int tpb = 256;
        k1_beamform<<<(total + tpb - 1)/tpb, tpb>>>(in, beam_id, tw, nw, out);
    }
    {   // K2: chunked scan, one thread per (chunk, b, f, n)
        int total = NB*NF*NNUL*NCHUNK;
        int tpb = 256;
        k2_scan<<<(total + tpb - 1)/tpb, tpb>>>(out);
    }
    {   // K3: apply ratio
        int total = DCF_SIZE;
        int tpb = 256;
        k3_ratio<<<(total + tpb - 1)/tpb, tpb>>>(out);
    }
}

// round 2
// speedup vs baseline: 1.8422x; 1.8422x over previous
#include <cuda_runtime.h>
#include <math.h>

#define NB   8
#define NT   500
#define NF   257
#define NC   8
#define NNUL 4
#define LOWF 5
#define HIGHF 70
#define DCF_SIZE (NB*NT*NF*NNUL)

#define A_    0.35f
#define OMA   0.65f
#define AOVER 0.53846156f   // a/(1-a)

#define RECF 12             // [r0 r1 r2 r3 i0 i1 i2 i3 pw pad pad pad] = 48B

// ---------------- scratch ----------------
__device__ float g_rec[(size_t)NB*NF*NT*RECF];   // 49.3 MB
__device__ float g_pre[NB*NT];
__device__ float g_aft[NB*NT*NNUL];

__device__ __forceinline__ float dot8(const float4 a0, const float4 a1,
                                      const float4 b0, const float4 b1) {
    return a0.x*b0.x + a0.y*b0.y + a0.z*b0.z + a0.w*b0.w
         + a1.x*b1.x + a1.y*b1.y + a1.z*b1.z + a1.w*b1.w;
}

// ---------------- K1: beamform, weights in registers, 16 t per thread -------
#define TPC 16
#define NTC 32   // ceil(500/16)

__global__ void k1_beamform(const float* __restrict__ in,
                            const int*   __restrict__ beam_id,
                            const float* __restrict__ tw,
                            const float* __restrict__ nw,
                            float* __restrict__ out) {
    int gid = blockIdx.x * blockDim.x + threadIdx.x;

    if (gid < NB*NT)      g_pre[gid] = 0.0f;
    if (gid < NB*NT*NNUL) g_aft[gid] = 0.0f;

    if (gid >= NB*NF*NTC) return;

    int f  = gid % NF;
    int r  = gid / NF;
    int b  = r % NB;
    int tc = r / NB;
    int t0 = tc * TPC;
    int t1 = min(t0 + TPC, NT);
    if (t0 >= NT) return;

    int beam = beam_id[b];

    // target weights -> registers (16 floats)
    const float* twrp = tw + ((beam*2 + 0)*NF + f)*NC;
    const float* twip = tw + ((beam*2 + 1)*NF + f)*NC;
    float4 twr0 = ((const float4*)twrp)[0], twr1 = ((const float4*)twrp)[1];
    float4 twi0 = ((const float4*)twip)[0], twi1 = ((const float4*)twip)[1];

    // null weights -> registers (64 floats)
    float4 nwr0[NNUL], nwr1[NNUL], nwi0[NNUL], nwi1[NNUL];
    #pragma unroll
    for (int n = 0; n < NNUL; n++) {
        const float* nwrp = nw + (((beam*NNUL + n)*2 + 0)*NF + f)*NC;
        const float* nwip = nw + (((beam*NNUL + n)*2 + 1)*NF + f)*NC;
        nwr0[n] = ((const float4*)nwrp)[0]; nwr1[n] = ((const float4*)nwrp)[1];
        nwi0[n] = ((const float4*)nwip)[0]; nwi1[n] = ((const float4*)nwip)[1];
    }

    float* recb = g_rec + ((size_t)(b*NF + f)*NT) * RECF;

    for (int t = t0; t < t1; t++) {
        const float* xrp = in + ((size_t)(b*NT + t)*2 + 0)*(NF*NC) + f*NC;
        const float* xip = in + ((size_t)(b*NT + t)*2 + 1)*(NF*NC) + f*NC;
        float4 xr0 = ((const float4*)xrp)[0], xr1 = ((const float4*)xrp)[1];
        float4 xi0 = ((const float4*)xip)[0], xi1 = ((const float4*)xip)[1];

        float tr = dot8(xr0,xr1, twr0,twr1) - dot8(xi0,xi1, twi0,twi1);
        float ti = dot8(xr0,xr1, twi0,twi1) + dot8(xi0,xi1, twr0,twr1);
        float pw = (dot8(xr0,xr1, xr0,xr1) + dot8(xi0,xi1, xi0,xi1)) * 0.125f;

        float prv[NNUL], piv[NNUL];
        #pragma unroll
        for (int n = 0; n < NNUL; n++) {
            float nr = dot8(xr0,xr1, nwr0[n],nwr1[n]) - dot8(xi0,xi1, nwi0[n],nwi1[n]);
            float ni = dot8(xr0,xr1, nwi0[n],nwi1[n]) + dot8(xi0,xi1, nwr0[n],nwr1[n]);
            prv[n] = tr*nr + ti*ni;
            piv[n] = ti*nr - tr*ni;
            if (t == 0) {
                // fold reference's t=0 quirk into the record:
                // phi_r0 = (1-a)*tr*nr + ti*ni  => pr0' = pr0 + (a/(1-a))*ti*ni
                // phi_i0 = (1-a)*ti*nr - tr*ni  => pi0' = pi0 - (a/(1-a))*tr*ni
                prv[n] += AOVER * (ti*ni);
                piv[n] -= AOVER * (tr*ni);
            }
        }

        float* rp = recb + t*RECF;
        ((float4*)rp)[0] = make_float4(prv[0], prv[1], prv[2], prv[3]);
        ((float4*)rp)[1] = make_float4(piv[0], piv[1], piv[2], piv[3]);
        ((float4*)rp)[2] = make_float4(pw, 0.f, 0.f, 0.f);

        out[DCF_SIZE + ((b*NT + t)*2 + 0)*NF + f] = tr;
        out[DCF_SIZE + ((b*NT + t)*2 + 1)*NF + f] = ti;
    }
}

// ---------------- K2: warp Kogge-Stone decayed scan, 32 t per iteration -----
// chunk 0: t in [0,256)  (8 iters)
// chunk 1: warmup iter [224,256) (discard) + t in [256,500) (8 iters)
__global__ void k2_scan(float* __restrict__ out) {
    int gtid = blockIdx.x * blockDim.x + threadIdx.x;
    int gw   = gtid >> 5;
    int lane = gtid & 31;
    const int NWARP = NB*NF*2;
    if (gw >= NWARP) return;

    int f     = gw % NF;
    int b     = (gw / NF) % NB;
    int chunk = gw / (NF*NB);

    const float* recb = g_rec + ((size_t)(b*NF + f)*NT) * RECF;
    float* qout = out + (size_t)(b*NT)*NF*NNUL + f*NNUL;  // + t*NF*NNUL
    bool inband = (f >= LOWF) && (f < HIGHF);

    // a^(lane+1)
    float pa = exp2f((float)(lane+1) * -1.5145732f);   // log2(0.35)

    float carry[9];
    #pragma unroll
    for (int k = 0; k < 9; k++) carry[k] = 0.0f;

    int T0    = chunk ? 224 : 0;
    int niter = chunk ? 9 : 8;

    for (int it = 0; it < niter; it++, T0 += 32) {
        bool wr = !(chunk && it == 0);
        int t  = T0 + lane;
        int tc = min(t, NT-1);
        const float* rp = recb + tc*RECF;
        float4 rr = ((const float4*)rp)[0];
        float4 ii = ((const float4*)rp)[1];
        float  pwv = rp[8];

        float u[9];
        u[0] = OMA*rr.x; u[1] = OMA*rr.y; u[2] = OMA*rr.z; u[3] = OMA*rr.w;
        u[4] = OMA*ii.x; u[5] = OMA*ii.y; u[6] = OMA*ii.z; u[7] = OMA*ii.w;
        u[8] = OMA*pwv;

        // decayed inclusive scan: y_lane = sum_{j<=lane} a^(lane-j) u_j
        const float AJ0 = 0.35f, AJ1 = 0.1225f, AJ2 = 0.01500625f,
                    AJ3 = 2.25187539e-4f, AJ4 = 5.07094278e-8f;
        #pragma unroll
        for (int k = 0; k < 9; k++) {
            float v;
            v = __shfl_up_sync(0xffffffffu, u[k], 1);
            if (lane >= 1)  u[k] = fmaf(AJ0, v, u[k]);
            v = __shfl_up_sync(0xffffffffu, u[k], 2);
            if (lane >= 2)  u[k] = fmaf(AJ1, v, u[k]);
            v = __shfl_up_sync(0xffffffffu, u[k], 4);
            if (lane >= 4)  u[k] = fmaf(AJ2, v, u[k]);
            v = __shfl_up_sync(0xffffffffu, u[k], 8);
            if (lane >= 8)  u[k] = fmaf(AJ3, v, u[k]);
            v = __shfl_up_sync(0xffffffffu, u[k], 16);
            if (lane >= 16) u[k] = fmaf(AJ4, v, u[k]);
        }

        float y[9];
        #pragma unroll
        for (int k = 0; k < 9; k++) y[k] = fmaf(pa, carry[k], u[k]);
        #pragma unroll
        for (int k = 0; k < 9; k++) carry[k] = __shfl_sync(0xffffffffu, y[k], 31);

        if (wr && t < NT) {
            float psd  = y[8];
            float rinv = __fdividef(1.0f, psd + 1e-13f);
            float ph[NNUL], q[NNUL];
            #pragma unroll
            for (int n = 0; n < NNUL; n++) {
                float p2 = fmaf(y[n], y[n], y[4+n]*y[4+n]);
                ph[n] = sqrtf(p2);
                q[n]  = fminf(fmaxf(ph[n]*rinv, 0.01f), 1.0f);
            }
            *(float4*)(qout + (size_t)t*NF*NNUL) = make_float4(q[0], q[1], q[2], q[3]);
            if (inband) {
                float* aftp = g_aft + (b*NT + t)*NNUL;
                #pragma unroll
                for (int n = 0; n < NNUL; n++) atomicAdd(aftp + n, ph[n]);
                atomicAdd(g_pre + b*NT + t, psd);
            }
        }
    }
}

// ---------------- K3: apply cross-frequency ratio (t >= 1), in place --------
__global__ void k3_ratio(float* __restrict__ out) {
    int idx = blockIdx.x * blockDim.x + threadIdx.x;   // one per (b,t,f)
    if (idx >= NB*NT*NF) return;
    int bt = idx / NF;
    int t  = bt % NT;
    if (t == 0) return;

    float4 q = *(float4*)(out + (size_t)idx*4);
    float rinv = __fdividef(1.0f, g_pre[bt] + 1e-10f);
    const float* aftp = g_aft + bt*NNUL;
    float4 r;
    r.x = sqrtf(q.x * fminf(fmaxf(aftp[0]*rinv, 0.01f), 1.0f));
    r.y = sqrtf(q.y * fminf(fmaxf(aftp[1]*rinv, 0.01f), 1.0f));
    r.z = sqrtf(q.z * fminf(fmaxf(aftp[2]*rinv, 0.01f), 1.0f));
    r.w = sqrtf(q.w * fminf(fmaxf(aftp[3]*rinv, 0.01f), 1.0f));
    *(float4*)(out + (size_t)idx*4) = r;
}

// ---------------- launcher ---------------------------------------------------
extern "C" void kernel_launch(void* const* d_in, const int* in_sizes, int n_in,
                              void* d_out, int out_size) {
    const float* in      = (const float*)d_in[0];
    const int*   beam_id = (const int*)  d_in[1];
    const float* tw      = (const float*)d_in[2];
    const float* nw      = (const float*)d_in[3];
    float* out = (float*)d_out;

    {   // K1
        int total = NB*NF*NTC;
        k1_beamform<<<(total + 255)/256, 256>>>(in, beam_id, tw, nw, out);
    }
    {   // K2
        int total = NB*NF*2*32;
        k2_scan<<<(total + 255)/256, 256>>>(out);
    }
    {   // K3
        int total = NB*NT*NF;
        k3_ratio<<<(total + 255)/256, 256>>>(out);
    }
}